// round 11
// baseline (speedup 1.0000x reference)
#include <cuda_runtime.h>
#include <cstdint>

// FlattenHead: segmented row compaction. FINAL (champion, R8 shape).
// x: [B=16, T=4096, D=1024] fp32, seq_lens: [16] int32.
// out rows = concat of x[b, 0:seq_lens[b]] per batch.
//
// Shape: 16 rows/block (64KB), 256 thr, occ 8, 4-deep ld/st groups, nc loads.
// Measured at the mixed R/W DRAM ceiling (5.1-5.4 TB/s, 64-68% of spec).
// Levers tested single-variable across R3-R10: load balance, reg-funded MLP,
// evict-first hints (hurts), chunk 8/16/32 (16 optimal band), nc path,
// persistent scheduler — all neutral or harmful. Run-to-run noise +/-1.5us.

static constexpr int B = 16;
static constexpr int T = 4096;
static constexpr int VEC_PER_ROW = 256;        // D/4 float4 per row
static constexpr int ROWS_PER_BLK = 16;
static constexpr int VECS_PER_BLK = ROWS_PER_BLK * VEC_PER_ROW;   // 4096
static constexpr int BLKS_PER_BATCH = T / ROWS_PER_BLK;           // 256
static constexpr int GROUP = 4;                // rows per ld/st group

__device__ __forceinline__ float4 ldnc4(const float4* p) {
    float4 v;
    asm volatile("ld.global.nc.v4.f32 {%0,%1,%2,%3}, [%4];"
                 : "=f"(v.x), "=f"(v.y), "=f"(v.z), "=f"(v.w) : "l"(p));
    return v;
}

__global__ __launch_bounds__(256, 8)
void flatten_head_kernel(const float4* __restrict__ x,
                         const int* __restrict__ seq_lens,
                         float4* __restrict__ out)
{
    const int blk = blockIdx.x;
    const int b   = blk >> 8;                  // / BLKS_PER_BATCH
    const int t0  = (blk & (BLKS_PER_BATCH - 1)) * ROWS_PER_BLK;

    const int len = seq_lens[b];
    if (t0 >= len) return;                     // fully-invalid chunk

    // Exclusive prefix of lens[0..b-1], 32-bit (sum <= 65536).
    int prefix = 0;
#pragma unroll
    for (int i = 0; i < B; ++i)
        prefix += (i < b) ? seq_lens[i] : 0;

    const int tid = threadIdx.x;
    const float4* __restrict__ src = x   + ((b * T + t0) * VEC_PER_ROW);
    float4*       __restrict__ dst = out + ((prefix + t0) * VEC_PER_ROW);

    const int nvalid = min(len - t0, ROWS_PER_BLK) * VEC_PER_ROW;

    if (nvalid == VECS_PER_BLK) {
        // Fast path: 4 groups of (4 nc-loads, 4 stores) — fits 32-reg budget.
#pragma unroll
        for (int g = 0; g < ROWS_PER_BLK / GROUP; ++g) {
            float4 r[GROUP];
#pragma unroll
            for (int k = 0; k < GROUP; ++k)
                r[k] = ldnc4(src + tid + (g * GROUP + k) * 256);
#pragma unroll
            for (int k = 0; k < GROUP; ++k)
                dst[tid + (g * GROUP + k) * 256] = r[k];
        }
    } else {
        // Boundary chunk (at most one per batch): predicated copy.
#pragma unroll
        for (int k = 0; k < ROWS_PER_BLK; ++k) {
            const int idx = tid + k * 256;
            if (idx < nvalid) dst[idx] = ldnc4(src + idx);
        }
    }
}

extern "C" void kernel_launch(void* const* d_in, const int* in_sizes, int n_in,
                              void* d_out, int out_size)
{
    (void)out_size;
    const float4* x;
    const int*    lens;
    if (in_sizes[0] == B) {                    // lens-first ordering (defensive)
        lens = (const int*)d_in[0];
        x    = (const float4*)((n_in > 1) ? d_in[1] : d_in[0]);
    } else {
        x    = (const float4*)d_in[0];
        lens = (const int*)((n_in > 1) ? d_in[1] : d_in[0]);
    }
    float4* out = (float4*)d_out;

    flatten_head_kernel<<<B * BLKS_PER_BATCH, 256>>>(x, lens, out);
}

// round 12
// speedup vs baseline: 1.0428x; 1.0428x over previous
#include <cuda_runtime.h>
#include <cstdint>

// FlattenHead: segmented row compaction. FINAL (champion shape, converged).
// x: [B=16, T=4096, D=1024] fp32, seq_lens: [16] int32.
// out rows = concat of x[b, 0:seq_lens[b]] per batch.
//
// Shape: 16 rows/block (64KB), 256 thr, occ 8, 4-deep ld/st groups, nc loads.
// Three samples of this exact source: kernel 30.0/31.5/30.5 us, DRAM 64-68%.
// This is the HBM3e mixed R/W ceiling (~5.3 TB/s); issue=6%, ALU=3% — no
// SM-side limiter. Levers refuted single-variable across R3-R11: load
// balance, reg-funded MLP, evict-first (hurts), chunk 8/32, persistent
// scheduler, occupancy trade. Traffic is algorithmically minimal.

static constexpr int B = 16;
static constexpr int T = 4096;
static constexpr int VEC_PER_ROW = 256;        // D/4 float4 per row
static constexpr int ROWS_PER_BLK = 16;
static constexpr int VECS_PER_BLK = ROWS_PER_BLK * VEC_PER_ROW;   // 4096
static constexpr int BLKS_PER_BATCH = T / ROWS_PER_BLK;           // 256
static constexpr int GROUP = 4;                // rows per ld/st group

__device__ __forceinline__ float4 ldnc4(const float4* p) {
    float4 v;
    asm volatile("ld.global.nc.v4.f32 {%0,%1,%2,%3}, [%4];"
                 : "=f"(v.x), "=f"(v.y), "=f"(v.z), "=f"(v.w) : "l"(p));
    return v;
}

__global__ __launch_bounds__(256, 8)
void flatten_head_kernel(const float4* __restrict__ x,
                         const int* __restrict__ seq_lens,
                         float4* __restrict__ out)
{
    const int blk = blockIdx.x;
    const int b   = blk >> 8;                  // / BLKS_PER_BATCH
    const int t0  = (blk & (BLKS_PER_BATCH - 1)) * ROWS_PER_BLK;

    const int len = seq_lens[b];
    if (t0 >= len) return;                     // fully-invalid chunk

    // Exclusive prefix of lens[0..b-1], 32-bit (sum <= 65536).
    int prefix = 0;
#pragma unroll
    for (int i = 0; i < B; ++i)
        prefix += (i < b) ? seq_lens[i] : 0;

    const int tid = threadIdx.x;
    const float4* __restrict__ src = x   + ((b * T + t0) * VEC_PER_ROW);
    float4*       __restrict__ dst = out + ((prefix + t0) * VEC_PER_ROW);

    const int nvalid = min(len - t0, ROWS_PER_BLK) * VEC_PER_ROW;

    if (nvalid == VECS_PER_BLK) {
        // Fast path: 4 groups of (4 nc-loads, 4 stores) — fits 32-reg budget.
#pragma unroll
        for (int g = 0; g < ROWS_PER_BLK / GROUP; ++g) {
            float4 r[GROUP];
#pragma unroll
            for (int k = 0; k < GROUP; ++k)
                r[k] = ldnc4(src + tid + (g * GROUP + k) * 256);
#pragma unroll
            for (int k = 0; k < GROUP; ++k)
                dst[tid + (g * GROUP + k) * 256] = r[k];
        }
    } else {
        // Boundary chunk (at most one per batch): predicated copy.
#pragma unroll
        for (int k = 0; k < ROWS_PER_BLK; ++k) {
            const int idx = tid + k * 256;
            if (idx < nvalid) dst[idx] = ldnc4(src + idx);
        }
    }
}

extern "C" void kernel_launch(void* const* d_in, const int* in_sizes, int n_in,
                              void* d_out, int out_size)
{
    (void)out_size;
    const float4* x;
    const int*    lens;
    if (in_sizes[0] == B) {                    // lens-first ordering (defensive)
        lens = (const int*)d_in[0];
        x    = (const float4*)((n_in > 1) ? d_in[1] : d_in[0]);
    } else {
        x    = (const float4*)d_in[0];
        lens = (const int*)((n_in > 1) ? d_in[1] : d_in[0]);
    }
    float4* out = (float4*)d_out;

    flatten_head_kernel<<<B * BLKS_PER_BATCH, 256>>>(x, lens, out);
}